// round 13
// baseline (speedup 1.0000x reference)
#include <cuda_runtime.h>
#include <cuda_fp16.h>
#include <mma.h>
#include <cstdint>

using namespace nvcuda;

// Problem constants
#define BB   2
#define SS   2048
#define DD   1024
#define HH   16
#define DHH  64
#define MM   (BB*SS)          // 4096
#define DHID 512              // mech hidden

#define LOG2E 1.44269504088896340736f

// ---------------- scratch (device globals; no allocation allowed) -------------
__device__ __half g_xh  [MM*DD];
__device__ __half g_Wqh [DD*DD];
__device__ __half g_Wkh [DD*DD];
__device__ __half g_Wvh [DD*DD];
__device__ __half g_Woh [DD*DD];
__device__ __half g_Wm1h[DHID*DD];
__device__ __half g_Qh  [MM*DD];   // [b*H+h][S][64]  (Q pre-scaled by log2e/8)
__device__ __half g_Kh  [MM*DD];
__device__ __half g_Vh  [MM*DD];
__device__ __half g_ctxh[MM*DD];   // [b][s][h*64+d]
__device__ float  g_part[4][MM];   // per-block logits partials (deterministic)
__device__ float  g_mech[MM];

// ---------------- cp.async helpers -------------------------------------------
__device__ __forceinline__ void cp16(void* s, const void* g) {
    asm volatile("cp.async.ca.shared.global [%0], [%1], 16;"
                 :: "r"((unsigned)__cvta_generic_to_shared(s)), "l"(g));
}
#define CP_COMMIT() asm volatile("cp.async.commit_group;")
#define CP_WAIT0()  asm volatile("cp.async.wait_group 0;")
#define CP_WAIT1()  asm volatile("cp.async.wait_group 1;")

// ---------------- mma.sync helpers --------------------------------------------
__device__ __forceinline__ void ldm_x4(uint32_t r[4], uint32_t addr) {
    asm volatile("ldmatrix.sync.aligned.m8n8.x4.shared.b16 {%0,%1,%2,%3}, [%4];"
                 : "=r"(r[0]), "=r"(r[1]), "=r"(r[2]), "=r"(r[3]) : "r"(addr));
}
__device__ __forceinline__ void ldm_x4_t(uint32_t r[4], uint32_t addr) {
    asm volatile("ldmatrix.sync.aligned.m8n8.x4.trans.shared.b16 {%0,%1,%2,%3}, [%4];"
                 : "=r"(r[0]), "=r"(r[1]), "=r"(r[2]), "=r"(r[3]) : "r"(addr));
}
__device__ __forceinline__ void mma16816(float c[4], const uint32_t a[4], uint32_t b0, uint32_t b1) {
    asm volatile("mma.sync.aligned.m16n8k16.row.col.f32.f16.f16.f32 "
                 "{%0,%1,%2,%3}, {%4,%5,%6,%7}, {%8,%9}, {%0,%1,%2,%3};"
                 : "+f"(c[0]), "+f"(c[1]), "+f"(c[2]), "+f"(c[3])
                 : "r"(a[0]), "r"(a[1]), "r"(a[2]), "r"(a[3]), "r"(b0), "r"(b1));
}

// ---------------- fp32 -> fp16 convert (single merged launch) ------------------
#define N4_X   (MM*DD/4)
#define N4_W   (DD*DD/4)
#define N4_WM1 (DHID*DD/4)
#define C0 N4_X
#define C1 (C0 + N4_W)
#define C2 (C1 + N4_W)
#define C3 (C2 + N4_W)
#define C4 (C3 + N4_W)
#define C5 (C4 + N4_WM1)
__global__ void f2h_all_kernel(
    const float4* __restrict__ x,  const float4* __restrict__ wq, const float4* __restrict__ wk,
    const float4* __restrict__ wv, const float4* __restrict__ wo, const float4* __restrict__ wm1)
{
    int i = blockIdx.x * blockDim.x + threadIdx.x;
    const float4* src; uint2* dst; int off;
    if      (i < C0) { src = x;   dst = (uint2*)g_xh;   off = i;      }
    else if (i < C1) { src = wq;  dst = (uint2*)g_Wqh;  off = i - C0; }
    else if (i < C2) { src = wk;  dst = (uint2*)g_Wkh;  off = i - C1; }
    else if (i < C3) { src = wv;  dst = (uint2*)g_Wvh;  off = i - C2; }
    else if (i < C4) { src = wo;  dst = (uint2*)g_Woh;  off = i - C3; }
    else if (i < C5) { src = wm1; dst = (uint2*)g_Wm1h; off = i - C4; }
    else return;
    float4 v = src[off];
    __half2 h0 = __floats2half2_rn(v.x, v.y);
    __half2 h1 = __floats2half2_rn(v.z, v.w);
    dst[off] = make_uint2(*(unsigned*)&h0, *(unsigned*)&h1);
}

// ---------------- 128x128-tile GEMM (BK=64, 3-stage ring): C = A * W^T + b ----
// mode 0: merged launch, grid z=0..3:
//   z=0/1/2: QKV projections (half out, head-split; Q scaled by log2e/8)
//   z=3 (y<4 only): mech layer1 + GELU + dot(Wm2) -> g_part[y][m]  (fused logits)
// mode 1: fp32 out row-major (output projection; uses Wa/ba)
// smem: 3 stages x (A 128x72h + B 128x72h) = 110592 B; 2 CTAs/SM (221 KB < 228 KB)
#define GSTG (2*128*72)                  // halves per stage (A+B)
__global__ void __launch_bounds__(256) gemm_kernel(
    const __half* __restrict__ A,
    const __half* __restrict__ Wa, const __half* __restrict__ Wb,
    const __half* __restrict__ Wc, const __half* __restrict__ Wd,
    const float*  __restrict__ ba, const float*  __restrict__ bb,
    const float*  __restrict__ bc, const float*  __restrict__ bd,
    const float*  __restrict__ Wm2,
    float* __restrict__ outF, int mode)
{
    bool mech = false;
    if (mode == 0 && blockIdx.z == 3) {
        if (blockIdx.y >= DHID/128) return;    // mech N=512: only y<4
        mech = true;
    }

    extern __shared__ __align__(16) char dyn[];
    __half* Ts = (__half*)dyn;           // 3 * GSTG halves
    float*  Cs = (float*)dyn;            // epilogue reuse: 128*132 floats = 67584 B

    const __half* Wp = Wa;
    const float*  bp = ba;
    __half* dstH = 0;
    float scale = 1.f;
    if (mode == 0) {
        int z = blockIdx.z;
        if (mech) { Wp = Wd; bp = bd; }
        else {
            Wp   = (z==0) ? Wa : (z==1) ? Wb : Wc;
            bp   = (z==0) ? ba : (z==1) ? bb : bc;
            dstH = (z==0) ? g_Qh : (z==1) ? g_Kh : g_Vh;
            scale = (z==0) ? 0.125f * LOG2E : 1.f;
        }
    }

    const int m0 = blockIdx.x * 128;
    const int n0 = blockIdx.y * 128;
    const int tid = threadIdx.x;
    const int wid = tid >> 5;
    const int wr  = wid & 1;       // m: 2 x 64
    const int wc  = wid >> 1;      // n: 4 x 32

    wmma::fragment<wmma::accumulator,16,16,16,float> acc[4][2];
    #pragma unroll
    for (int i = 0; i < 4; ++i) { wmma::fill_fragment(acc[i][0], 0.f); wmma::fill_fragment(acc[i][1], 0.f); }

    #define GEMM_LOAD(kt, st) do {                                                  \
        const int k0_ = (kt)*64;                                                    \
        __half* as_ = Ts + (st)*GSTG;                                               \
        __half* bs_ = as_ + 128*72;                                                 \
        _Pragma("unroll")                                                           \
        for (int i_ = 0; i_ < 4; ++i_) {                                            \
            int idx_ = tid + i_*256;                                                \
            int r_ = idx_ >> 3, c8_ = idx_ & 7;                                     \
            cp16(as_ + r_*72 + c8_*8, A  + (size_t)(m0+r_)*1024 + k0_ + c8_*8);     \
            cp16(bs_ + r_*72 + c8_*8, Wp + (size_t)(n0+r_)*1024 + k0_ + c8_*8);     \
        }                                                                           \
        CP_COMMIT();                                                                \
    } while(0)

    GEMM_LOAD(0, 0);
    GEMM_LOAD(1, 1);

    int st = 0;
    for (int kt = 0; kt < 16; ++kt) {
        if (kt < 15) CP_WAIT1(); else CP_WAIT0();
        __syncthreads();
        if (kt < 14) {
            int st2 = st + 2; if (st2 >= 3) st2 -= 3;   // holds tile kt-1: consumed
            GEMM_LOAD(kt+2, st2);
        }
        const __half* as = Ts + st*GSTG;
        const __half* bs = as + 128*72;
        #pragma unroll
        for (int kk = 0; kk < 4; ++kk) {
            wmma::fragment<wmma::matrix_a,16,16,16,__half,wmma::row_major> af[4];
            #pragma unroll
            for (int fm = 0; fm < 4; ++fm)
                wmma::load_matrix_sync(af[fm], as + (wr*64 + fm*16)*72 + kk*16, 72);
            #pragma unroll
            for (int fn = 0; fn < 2; ++fn) {
                wmma::fragment<wmma::matrix_b,16,16,16,__half,wmma::col_major> bf;
                wmma::load_matrix_sync(bf, bs + (wc*32 + fn*16)*72 + kk*16, 72);
                #pragma unroll
                for (int fm = 0; fm < 4; ++fm)
                    wmma::mma_sync(acc[fm][fn], af[fm], bf, acc[fm][fn]);
            }
        }
        if (++st == 3) st = 0;
    }
    __syncthreads();   // done with tiles; Cs aliases them

    #pragma unroll
    for (int fm = 0; fm < 4; ++fm)
        #pragma unroll
        for (int fn = 0; fn < 2; ++fn)
            wmma::store_matrix_sync(Cs + (wr*64 + fm*16)*132 + wc*32 + fn*16, acc[fm][fn], 132, wmma::mem_row_major);
    __syncthreads();

    const int row = tid >> 1;
    const int cb  = (tid & 1) * 64;
    const int m   = m0 + row;
    if (mode == 1) {
        float* dst = outF + (size_t)m*DD + n0 + cb;
        #pragma unroll
        for (int c = 0; c < 64; ++c)
            dst[c] = Cs[row*132 + cb + c] + bp[n0 + cb + c];
    } else if (!mech) {
        int b = m >> 11, s = m & 2047;
        int h = (n0 + cb) >> 6;
        __half* dst = dstH + (((size_t)(b*HH + h))*SS + s)*DHH;
        #pragma unroll
        for (int c0 = 0; c0 < 64; c0 += 8) {
            __half hv[8];
            #pragma unroll
            for (int e = 0; e < 8; ++e)
                hv[e] = __float2half((Cs[row*132 + cb + c0 + e] + bp[n0 + cb + c0 + e]) * scale);
            *(uint4*)&dst[c0] = *(uint4*)hv;
        }
    } else {
        // mech: GELU then partial dot with Wm2; deterministic per-block partial
        float p = 0.f;
        #pragma unroll
        for (int c = 0; c < 64; ++c) {
            int n = n0 + cb + c;
            float v = Cs[row*132 + cb + c] + bp[n];
            float gl = 0.5f * v * (1.f + erff(v * 0.70710678118654752f));
            p += gl * Wm2[n];
        }
        p += __shfl_xor_sync(0xffffffffu, p, 1);   // combine the row's two halves
        if ((tid & 1) == 0) g_part[blockIdx.y][m] = p;
    }
}

// ---------------- per-batch softmax over S=2048 (sums the 4 logits partials) ---
// bm2 is omitted: a constant shift cancels in softmax.
__global__ void mech_softmax_kernel(float* __restrict__ out_tail) {
    int b = blockIdx.x;
    int tid = threadIdx.x;           // 256
    __shared__ float red[256];
    __shared__ float lg[SS];
    for (int i = tid; i < SS; i += 256) {
        int m = b*SS + i;
        lg[i] = g_part[0][m] + g_part[1][m] + g_part[2][m] + g_part[3][m];
    }
    __syncthreads();
    float mx = -1e30f;
    for (int i = tid; i < SS; i += 256) mx = fmaxf(mx, lg[i]);
    red[tid] = mx; __syncthreads();
    for (int s = 128; s > 0; s >>= 1) { if (tid < s) red[tid] = fmaxf(red[tid], red[tid+s]); __syncthreads(); }
    mx = red[0]; __syncthreads();
    float sm = 0.f;
    for (int i = tid; i < SS; i += 256) sm += __expf(lg[i] - mx);
    red[tid] = sm; __syncthreads();
    for (int s = 128; s > 0; s >>= 1) { if (tid < s) red[tid] += red[tid+s]; __syncthreads(); }
    float inv = 1.f / red[0];
    for (int i = tid; i < SS; i += 256) {
        float v = __expf(lg[i] - mx) * inv;
        g_mech[b*SS + i] = v;
        out_tail[b*SS + i] = v;
    }
}

// ---------------- attention: mma.sync, register-resident S/P/O ----------------
// 128 queries/block, 8 warps (16 q-rows each), 64-key tiles, 3-stage cp.async KV ring.
// Q pre-scaled by log2e/8; bias pre-scaled by 2*log2e -> exp2f. Unnormalized accumulation.
// smem: Qs 128x72h | Ks 3x64x72h | Vs 3x64x72h | bias 2048f = 81920 B; 2 CTAs/SM.
__global__ void __launch_bounds__(256, 2) attn_kernel(const int* __restrict__ mask) {
    extern __shared__ __align__(16) char dyn[];
    __half* Qs  = (__half*)dyn;              // 128*72
    __half* Ks  = Qs + 128*72;               // 3*64*72
    __half* Vs  = Ks + 3*64*72;              // 3*64*72
    float*  bias= (float*)(Vs + 3*64*72);    // 2048

    const int q0  = blockIdx.x * 128;
    const int bh  = blockIdx.y;
    const int b   = bh >> 4;
    const int h   = bh & 15;
    const int tid = threadIdx.x;
    const int w   = tid >> 5;
    const int lane= tid & 31;
    const int g   = lane >> 2;
    const int t4  = lane & 3;

    const int arow = (lane & 7) | (((lane >> 3) & 1) << 3);
    const int ac8  = lane >> 4;
    const int brow = (lane & 7) | ((lane >> 4) << 3);
    const int bc8  = (lane >> 3) & 1;

    const __half* Qg = g_Qh + (size_t)bh * SS * DHH;
    const __half* Kg = g_Kh + (size_t)bh * SS * DHH;
    const __half* Vg = g_Vh + (size_t)bh * SS * DHH;

    #pragma unroll
    for (int i = 0; i < 4; ++i) {
        int idx = tid + i*256;
        int r = idx >> 3, c8 = idx & 7;
        *(uint4*)(Qs + r*72 + c8*8) = *(const uint4*)(Qg + (size_t)(q0+r)*DHH + c8*8);
    }
    for (int i = tid; i < SS; i += 256)
        bias[i] = mask[b*SS + i] ? (2.0f * LOG2E) * g_mech[b*SS + i] : -1e30f;

    #define KV_LOAD(kt, st) do {                                                  \
        const int k0_ = (kt)*64;                                                  \
        __half* ks_ = Ks + (st)*64*72;                                            \
        __half* vs_ = Vs + (st)*64*72;                                            \
        _Pragma("unroll")                                                         \
        for (int i_ = 0; i_ < 2; ++i_) {                                          \
            int idx_ = tid + i_*256;                                              \
            int r_ = idx_ >> 3, c8_ = idx_ & 7;                                   \
            cp16(ks_ + r_*72 + c8_*8, Kg + (size_t)(k0_+r_)*DHH + c8_*8);         \
            cp16(vs_ + r_*72 + c8_*8, Vg + (size_t)(k0_+r_)*DHH + c8_*8);         \
        }                                                                         \
    } while(0)

    KV_LOAD(0, 0); CP_COMMIT();
    KV_LOAD(1, 1); CP_COMMIT();
    __syncthreads();                 // Q + bias visible

    uint32_t qa[4][4];
    #pragma unroll
    for (int kk = 0; kk < 4; ++kk) {
        uint32_t addr = (unsigned)__cvta_generic_to_shared(
            Qs + (w*16 + arow)*72 + kk*16 + ac8*8);
        ldm_x4(qa[kk], addr);
    }

    float oc[8][4];
    #pragma unroll
    for (int j = 0; j < 8; ++j) { oc[j][0]=0.f; oc[j][1]=0.f; oc[j][2]=0.f; oc[j][3]=0.f; }
    float rs0 = 0.f, rs1 = 0.f;

    const uint32_t KsA = (unsigned)__cvta_generic_to_shared(Ks);
    const uint32_t VsA = (unsigned)__cvta_generic_to_shared(Vs);

    int st = 0;
    for (int kt = 0; kt < 32; ++kt) {
        if (kt < 31) CP_WAIT1(); else CP_WAIT0();
        __syncthreads();
        if (kt < 30) {
            int st2 = st + 2; if (st2 >= 3) st2 -= 3;
            KV_LOAD(kt+2, st2); CP_COMMIT();
        }
        const uint32_t ksb = KsA + st*64*72*2;
        const uint32_t vsb = VsA + st*64*72*2;
        const int k0 = kt*64;

        float sc[8][4];
        #pragma unroll
        for (int j = 0; j < 8; ++j) { sc[j][0]=0.f; sc[j][1]=0.f; sc[j][2]=0.f; sc[j][3]=0.f; }
        #pragma unroll
        for (int kk = 0; kk < 4; ++kk) {
            #pragma unroll
            for (int jj = 0; jj < 4; ++jj) {
                uint32_t kb[4];
                ldm_x4(kb, ksb + ((jj*16 + brow)*72 + kk*16 + bc8*8)*2);
                mma16816(sc[jj*2],   qa[kk], kb[0], kb[1]);
                mma16816(sc[jj*2+1], qa[kk], kb[2], kb[3]);
            }
        }

        uint32_t ph[8][2];
        #pragma unroll
        for (int j = 0; j < 8; ++j) {
            float2 bv = *(const float2*)&bias[k0 + j*8 + t4*2];
            float p0 = exp2f(sc[j][0] + bv.x);
            float p1 = exp2f(sc[j][1] + bv.y);
            float p2 = exp2f(sc[j][2] + bv.x);
            float p3 = exp2f(sc[j][3] + bv.y);
            rs0 += p0 + p1;
            rs1 += p2 + p3;
            __half2 h0 = __floats2half2_rn(p0, p1);
            __half2 h1 = __floats2half2_rn(p2, p3);
            ph[j][0] = *(uint32_t*)&h0;
            ph[j][1] = *(uint32_t*)&h1;
        }

        #pragma unroll
        for (int kp = 0; kp < 4; ++kp) {
            uint32_t pa[4] = { ph[2*kp][0], ph[2*kp][1], ph[2*kp+1][0], ph[2*kp+1][1] };
            #pragma unroll
            for (int jj = 0; jj < 4; ++jj) {
                uint32_t vb[4];
                ldm_x4_t(vb, vsb + ((kp*16 + arow)*72 + jj*16 + ac8*8)*2);
                mma16816(oc[jj*2],   pa, vb[0], vb[1]);
                mma16816(oc[jj*2+1], pa, vb[2], vb[3]);
            }
        }
        if (++st == 3) st = 0;
    }

    rs0 += __shfl_xor_sync(0xffffffffu, rs0, 1);
    rs0 += __shfl_xor_sync(0xffffffffu, rs0, 2);
    rs1 += __shfl_xor_sync(0xffffffffu, rs1, 1);
    rs1 += __shfl_xor_sync(0xffffffffu, rs1, 2);
    float inv0 = 1.f / rs0;
    float inv1 = 1.f / rs1;

    __half* d0 = g_ctxh + ((size_t)(b*SS + q0 + w*16 + g    ))*DD + h*DHH;
    __half* d1 = g_ctxh + ((size_t)(b*SS + q0 + w*16 + g + 8))*DD + h*DHH;
    #pragma unroll
    for (int j = 0; j < 8; ++j) {
        __half2 u0 = __floats2half2_rn(oc[j][0]*inv0, oc[j][1]*inv0);
        __half2 u1 = __floats2half2_rn(oc[j][2]*inv1, oc[j][3]*inv1);
        *(__half2*)&d0[j*8 + t4*2] = u0;
        *(__half2*)&d1[j*8 + t4*2] = u1;
    }
}

// ---------------- host launcher ----------------------------------------------
static void* symaddr(const void* sym) { void* p = 0; cudaGetSymbolAddress(&p, sym); return p; }

#define GEMM_SMEM (3*GSTG*2)    // 110592
#define ATTN_SMEM 81920

extern "C" void kernel_launch(void* const* d_in, const int* in_sizes, int n_in,
                              void* d_out, int out_size) {
    const float* x   = (const float*)d_in[0];
    const int*   mask= (const int*)  d_in[1];
    const float* Wq  = (const float*)d_in[2];
    const float* bq  = (const float*)d_in[3];
    const float* Wk  = (const float*)d_in[4];
    const float* bk  = (const float*)d_in[5];
    const float* Wv  = (const float*)d_in[6];
    const float* bv  = (const float*)d_in[7];
    const float* Wo  = (const float*)d_in[8];
    const float* bo  = (const float*)d_in[9];
    const float* Wm1 = (const float*)d_in[10];
    const float* bm1 = (const float*)d_in[11];
    const float* Wm2 = (const float*)d_in[12];
    float* out = (float*)d_out;

    __half* xh   = (__half*)symaddr(g_xh);
    __half* Wqh  = (__half*)symaddr(g_Wqh);
    __half* Wkh  = (__half*)symaddr(g_Wkh);
    __half* Wvh  = (__half*)symaddr(g_Wvh);
    __half* Woh  = (__half*)symaddr(g_Woh);
    __half* Wm1h = (__half*)symaddr(g_Wm1h);
    __half* ctxh = (__half*)symaddr(g_ctxh);

    cudaFuncSetAttribute(gemm_kernel, cudaFuncAttributeMaxDynamicSharedMemorySize, GEMM_SMEM);
    cudaFuncSetAttribute(attn_kernel, cudaFuncAttributeMaxDynamicSharedMemorySize, ATTN_SMEM);

    // 1. convert all fp32 inputs to fp16 in one launch
    f2h_all_kernel<<<(C5 + 255)/256, 256>>>(
        (const float4*)x, (const float4*)Wq, (const float4*)Wk,
        (const float4*)Wv, (const float4*)Wo, (const float4*)Wm1);

    // 2. merged QKV + mech-MLP GEMM (z=0..2: QKV; z=3: mech layer1+GELU+logits partials)
    gemm_kernel<<<dim3(MM/128, DD/128, 4), 256, GEMM_SMEM>>>(
        xh, Wqh, Wkh, Wvh, Wm1h, bq, bk, bv, bm1, Wm2, 0, 0);

    // 3. mech softmax (sums logits partials; bm2 cancels in softmax)
    mech_softmax_kernel<<<BB, 256>>>(out + (size_t)MM*DD);

    // 4. attention
    attn_kernel<<<dim3(SS/128, BB*HH), 256, ATTN_SMEM>>>(mask);

    // 5. output projection -> d_out
    gemm_kernel<<<dim3(MM/128, DD/128, 1), 256, GEMM_SMEM>>>(
        (const __half*)ctxh, Woh, Woh, Woh, Woh, bo, bo, bo, bo, Wm2, out, 1);
}

// round 14
// speedup vs baseline: 1.0958x; 1.0958x over previous
#include <cuda_runtime.h>
#include <cuda_fp16.h>
#include <mma.h>
#include <cstdint>

using namespace nvcuda;

// Problem constants
#define BB   2
#define SS   2048
#define DD   1024
#define HH   16
#define DHH  64
#define MM   (BB*SS)          // 4096
#define DHID 512              // mech hidden

#define LOG2E 1.44269504088896340736f

// ---------------- scratch (device globals; no allocation allowed) -------------
__device__ __half g_xh  [MM*DD];
__device__ __half g_Wqh [DD*DD];
__device__ __half g_Wkh [DD*DD];
__device__ __half g_Wvh [DD*DD];
__device__ __half g_Woh [DD*DD];
__device__ __half g_Wm1h[DHID*DD];
__device__ __half g_Qh  [MM*DD];   // [b*H+h][S][64]  (Q pre-scaled by log2e/8)
__device__ __half g_Kh  [MM*DD];
__device__ __half g_Vh  [MM*DD];
__device__ __half g_ctxh[MM*DD];   // [b][s][h*64+d]
__device__ float  g_part[4][MM];   // per-block logits partials (deterministic)
__device__ float  g_mech[MM];

// ---------------- cp.async helpers -------------------------------------------
__device__ __forceinline__ void cp16(void* s, const void* g) {
    asm volatile("cp.async.ca.shared.global [%0], [%1], 16;"
                 :: "r"((unsigned)__cvta_generic_to_shared(s)), "l"(g));
}
#define CP_COMMIT() asm volatile("cp.async.commit_group;")
#define CP_WAIT0()  asm volatile("cp.async.wait_group 0;")
#define CP_WAIT1()  asm volatile("cp.async.wait_group 1;")

// ---------------- mma.sync helpers --------------------------------------------
__device__ __forceinline__ void ldm_x4(uint32_t r[4], uint32_t addr) {
    asm volatile("ldmatrix.sync.aligned.m8n8.x4.shared.b16 {%0,%1,%2,%3}, [%4];"
                 : "=r"(r[0]), "=r"(r[1]), "=r"(r[2]), "=r"(r[3]) : "r"(addr));
}
__device__ __forceinline__ void ldm_x4_t(uint32_t r[4], uint32_t addr) {
    asm volatile("ldmatrix.sync.aligned.m8n8.x4.trans.shared.b16 {%0,%1,%2,%3}, [%4];"
                 : "=r"(r[0]), "=r"(r[1]), "=r"(r[2]), "=r"(r[3]) : "r"(addr));
}
__device__ __forceinline__ void mma16816(float c[4], const uint32_t a[4], uint32_t b0, uint32_t b1) {
    asm volatile("mma.sync.aligned.m16n8k16.row.col.f32.f16.f16.f32 "
                 "{%0,%1,%2,%3}, {%4,%5,%6,%7}, {%8,%9}, {%0,%1,%2,%3};"
                 : "+f"(c[0]), "+f"(c[1]), "+f"(c[2]), "+f"(c[3])
                 : "r"(a[0]), "r"(a[1]), "r"(a[2]), "r"(a[3]), "r"(b0), "r"(b1));
}

// ---------------- fp32 -> fp16 convert (single merged launch) ------------------
#define N4_X   (MM*DD/4)
#define N4_W   (DD*DD/4)
#define N4_WM1 (DHID*DD/4)
#define C0 N4_X
#define C1 (C0 + N4_W)
#define C2 (C1 + N4_W)
#define C3 (C2 + N4_W)
#define C4 (C3 + N4_W)
#define C5 (C4 + N4_WM1)
__global__ void f2h_all_kernel(
    const float4* __restrict__ x,  const float4* __restrict__ wq, const float4* __restrict__ wk,
    const float4* __restrict__ wv, const float4* __restrict__ wo, const float4* __restrict__ wm1)
{
    int i = blockIdx.x * blockDim.x + threadIdx.x;
    const float4* src; uint2* dst; int off;
    if      (i < C0) { src = x;   dst = (uint2*)g_xh;   off = i;      }
    else if (i < C1) { src = wq;  dst = (uint2*)g_Wqh;  off = i - C0; }
    else if (i < C2) { src = wk;  dst = (uint2*)g_Wkh;  off = i - C1; }
    else if (i < C3) { src = wv;  dst = (uint2*)g_Wvh;  off = i - C2; }
    else if (i < C4) { src = wo;  dst = (uint2*)g_Woh;  off = i - C3; }
    else if (i < C5) { src = wm1; dst = (uint2*)g_Wm1h; off = i - C4; }
    else return;
    float4 v = src[off];
    __half2 h0 = __floats2half2_rn(v.x, v.y);
    __half2 h1 = __floats2half2_rn(v.z, v.w);
    dst[off] = make_uint2(*(unsigned*)&h0, *(unsigned*)&h1);
}

// ---------------- 128x128-tile GEMM (BK=64, 2-stage): C = A * W^T + b ----------
// (R10 config — frozen: 2 CTAs/SM makes deeper pipelines counterproductive)
// mode 0: merged launch, grid z=0..3:
//   z=0/1/2: QKV projections (half out, head-split; Q scaled by log2e/8)
//   z=3 (y<4 only): mech layer1 + GELU + dot(Wm2) -> g_part[y][m]  (fused logits)
// mode 1: fp32 out row-major (output projection; uses Wa/ba)
__global__ void __launch_bounds__(256) gemm_kernel(
    const __half* __restrict__ A,
    const __half* __restrict__ Wa, const __half* __restrict__ Wb,
    const __half* __restrict__ Wc, const __half* __restrict__ Wd,
    const float*  __restrict__ ba, const float*  __restrict__ bb,
    const float*  __restrict__ bc, const float*  __restrict__ bd,
    const float*  __restrict__ Wm2,
    float* __restrict__ outF, int mode)
{
    bool mech = false;
    if (mode == 0 && blockIdx.z == 3) {
        if (blockIdx.y >= DHID/128) return;    // mech N=512: only y<4
        mech = true;
    }

    extern __shared__ __align__(16) char dyn[];
    __half* As = (__half*)dyn;           // 2 * 128*72
    __half* Bs = As + 2*128*72;          // 2 * 128*72
    float*  Cs = (float*)dyn;            // epilogue reuse: 128*132 floats

    const __half* Wp = Wa;
    const float*  bp = ba;
    __half* dstH = 0;
    float scale = 1.f;
    if (mode == 0) {
        int z = blockIdx.z;
        if (mech) { Wp = Wd; bp = bd; }
        else {
            Wp   = (z==0) ? Wa : (z==1) ? Wb : Wc;
            bp   = (z==0) ? ba : (z==1) ? bb : bc;
            dstH = (z==0) ? g_Qh : (z==1) ? g_Kh : g_Vh;
            scale = (z==0) ? 0.125f * LOG2E : 1.f;
        }
    }

    const int m0 = blockIdx.x * 128;
    const int n0 = blockIdx.y * 128;
    const int tid = threadIdx.x;
    const int wid = tid >> 5;
    const int wr  = wid & 1;       // m: 2 x 64
    const int wc  = wid >> 1;      // n: 4 x 32

    wmma::fragment<wmma::accumulator,16,16,16,float> acc[4][2];
    #pragma unroll
    for (int i = 0; i < 4; ++i) { wmma::fill_fragment(acc[i][0], 0.f); wmma::fill_fragment(acc[i][1], 0.f); }

    #define GEMM_LOAD(kt, st) do {                                                  \
        const int k0_ = (kt)*64;                                                    \
        __half* as_ = As + (st)*128*72;                                             \
        __half* bs_ = Bs + (st)*128*72;                                             \
        _Pragma("unroll")                                                           \
        for (int i_ = 0; i_ < 4; ++i_) {                                            \
            int idx_ = tid + i_*256;                                                \
            int r_ = idx_ >> 3, c8_ = idx_ & 7;                                     \
            cp16(as_ + r_*72 + c8_*8, A  + (size_t)(m0+r_)*1024 + k0_ + c8_*8);     \
            cp16(bs_ + r_*72 + c8_*8, Wp + (size_t)(n0+r_)*1024 + k0_ + c8_*8);     \
        }                                                                           \
    } while(0)

    GEMM_LOAD(0, 0); CP_COMMIT();

    for (int kt = 0; kt < 16; ++kt) {
        CP_WAIT0();
        __syncthreads();
        if (kt < 15) { GEMM_LOAD(kt+1, (kt+1)&1); CP_COMMIT(); }
        const __half* as = As + (kt&1)*128*72;
        const __half* bs = Bs + (kt&1)*128*72;
        #pragma unroll
        for (int kk = 0; kk < 4; ++kk) {
            wmma::fragment<wmma::matrix_a,16,16,16,__half,wmma::row_major> af[4];
            #pragma unroll
            for (int fm = 0; fm < 4; ++fm)
                wmma::load_matrix_sync(af[fm], as + (wr*64 + fm*16)*72 + kk*16, 72);
            #pragma unroll
            for (int fn = 0; fn < 2; ++fn) {
                wmma::fragment<wmma::matrix_b,16,16,16,__half,wmma::col_major> bf;
                wmma::load_matrix_sync(bf, bs + (wc*32 + fn*16)*72 + kk*16, 72);
                #pragma unroll
                for (int fm = 0; fm < 4; ++fm)
                    wmma::mma_sync(acc[fm][fn], af[fm], bf, acc[fm][fn]);
            }
        }
    }
    __syncthreads();

    #pragma unroll
    for (int fm = 0; fm < 4; ++fm)
        #pragma unroll
        for (int fn = 0; fn < 2; ++fn)
            wmma::store_matrix_sync(Cs + (wr*64 + fm*16)*132 + wc*32 + fn*16, acc[fm][fn], 132, wmma::mem_row_major);
    __syncthreads();

    const int row = tid >> 1;
    const int cb  = (tid & 1) * 64;
    const int m   = m0 + row;
    if (mode == 1) {
        float* dst = outF + (size_t)m*DD + n0 + cb;
        #pragma unroll
        for (int c = 0; c < 64; ++c)
            dst[c] = Cs[row*132 + cb + c] + bp[n0 + cb + c];
    } else if (!mech) {
        int b = m >> 11, s = m & 2047;
        int h = (n0 + cb) >> 6;
        __half* dst = dstH + (((size_t)(b*HH + h))*SS + s)*DHH;
        #pragma unroll
        for (int c0 = 0; c0 < 64; c0 += 8) {
            __half hv[8];
            #pragma unroll
            for (int e = 0; e < 8; ++e)
                hv[e] = __float2half((Cs[row*132 + cb + c0 + e] + bp[n0 + cb + c0 + e]) * scale);
            *(uint4*)&dst[c0] = *(uint4*)hv;
        }
    } else {
        float p = 0.f;
        #pragma unroll
        for (int c = 0; c < 64; ++c) {
            int n = n0 + cb + c;
            float v = Cs[row*132 + cb + c] + bp[n];
            float gl = 0.5f * v * (1.f + erff(v * 0.70710678118654752f));
            p += gl * Wm2[n];
        }
        p += __shfl_xor_sync(0xffffffffu, p, 1);
        if ((tid & 1) == 0) g_part[blockIdx.y][m] = p;
    }
}

// ---------------- per-batch softmax over S=2048 (sums the 4 logits partials) ---
__global__ void mech_softmax_kernel(float* __restrict__ out_tail) {
    int b = blockIdx.x;
    int tid = threadIdx.x;           // 256
    __shared__ float red[256];
    __shared__ float lg[SS];
    for (int i = tid; i < SS; i += 256) {
        int m = b*SS + i;
        lg[i] = g_part[0][m] + g_part[1][m] + g_part[2][m] + g_part[3][m];
    }
    __syncthreads();
    float mx = -1e30f;
    for (int i = tid; i < SS; i += 256) mx = fmaxf(mx, lg[i]);
    red[tid] = mx; __syncthreads();
    for (int s = 128; s > 0; s >>= 1) { if (tid < s) red[tid] = fmaxf(red[tid], red[tid+s]); __syncthreads(); }
    mx = red[0]; __syncthreads();
    float sm = 0.f;
    for (int i = tid; i < SS; i += 256) sm += __expf(lg[i] - mx);
    red[tid] = sm; __syncthreads();
    for (int s = 128; s > 0; s >>= 1) { if (tid < s) red[tid] += red[tid+s]; __syncthreads(); }
    float inv = 1.f / red[0];
    for (int i = tid; i < SS; i += 256) {
        float v = __expf(lg[i] - mx) * inv;
        g_mech[b*SS + i] = v;
        out_tail[b*SS + i] = v;
    }
}

// ---------------- attention: 4 warps x 32 q-rows (K/V fragment reuse 2x) -------
// 128 queries/block, 128 threads, 64-key tiles, 3-stage cp.async KV ring.
// Each ldmatrix'd K/V fragment feeds TWO 16-row MMA row-halves -> LDSM/flop halved.
// smem: Qs 128x72h | Ks 3x64x72h | Vs 3x64x72h | bias 2048f = 81920 B; 2 CTAs/SM.
__global__ void __launch_bounds__(128, 2) attn_kernel(const int* __restrict__ mask) {
    extern __shared__ __align__(16) char dyn[];
    __half* Qs  = (__half*)dyn;              // 128*72
    __half* Ks  = Qs + 128*72;               // 3*64*72
    __half* Vs  = Ks + 3*64*72;              // 3*64*72
    float*  bias= (float*)(Vs + 3*64*72);    // 2048

    const int q0  = blockIdx.x * 128;
    const int bh  = blockIdx.y;
    const int b   = bh >> 4;
    const int h   = bh & 15;
    const int tid = threadIdx.x;
    const int w   = tid >> 5;          // 0..3, owns rows [w*32, w*32+32)
    const int lane= tid & 31;
    const int g   = lane >> 2;
    const int t4  = lane & 3;

    const int arow = (lane & 7) | (((lane >> 3) & 1) << 3);
    const int ac8  = lane >> 4;
    const int brow = (lane & 7) | ((lane >> 4) << 3);
    const int bc8  = (lane >> 3) & 1;

    const __half* Qg = g_Qh + (size_t)bh * SS * DHH;
    const __half* Kg = g_Kh + (size_t)bh * SS * DHH;
    const __half* Vg = g_Vh + (size_t)bh * SS * DHH;

    // Q tile: 1024 chunks / 128 threads = 8 iters
    #pragma unroll
    for (int i = 0; i < 8; ++i) {
        int idx = tid + i*128;
        int r = idx >> 3, c8 = idx & 7;
        *(uint4*)(Qs + r*72 + c8*8) = *(const uint4*)(Qg + (size_t)(q0+r)*DHH + c8*8);
    }
    for (int i = tid; i < SS; i += 128)
        bias[i] = mask[b*SS + i] ? (2.0f * LOG2E) * g_mech[b*SS + i] : -1e30f;

    #define KV_LOAD(kt, st) do {                                                  \
        const int k0_ = (kt)*64;                                                  \
        __half* ks_ = Ks + (st)*64*72;                                            \
        __half* vs_ = Vs + (st)*64*72;                                            \
        _Pragma("unroll")                                                         \
        for (int i_ = 0; i_ < 4; ++i_) {                                          \
            int idx_ = tid + i_*128;                                              \
            int r_ = idx_ >> 3, c8_ = idx_ & 7;                                   \
            cp16(ks_ + r_*72 + c8_*8, Kg + (size_t)(k0_+r_)*DHH + c8_*8);         \
            cp16(vs_ + r_*72 + c8_*8, Vg + (size_t)(k0_+r_)*DHH + c8_*8);         \
        }                                                                         \
    } while(0)

    KV_LOAD(0, 0); CP_COMMIT();
    KV_LOAD(1, 1); CP_COMMIT();
    __syncthreads();                 // Q + bias visible

    // Q fragments: 2 row-halves x 4 k-steps
    uint32_t qa[4][2][4];
    #pragma unroll
    for (int kk = 0; kk < 4; ++kk)
        #pragma unroll
        for (int r2 = 0; r2 < 2; ++r2) {
            uint32_t addr = (unsigned)__cvta_generic_to_shared(
                Qs + (w*32 + r2*16 + arow)*72 + kk*16 + ac8*8);
            ldm_x4(qa[kk][r2], addr);
        }

    float oc[2][8][4];
    #pragma unroll
    for (int r2 = 0; r2 < 2; ++r2)
        #pragma unroll
        for (int j = 0; j < 8; ++j) { oc[r2][j][0]=0.f; oc[r2][j][1]=0.f; oc[r2][j][2]=0.f; oc[r2][j][3]=0.f; }
    float rsv[2][2] = {{0.f,0.f},{0.f,0.f}};

    const uint32_t KsA = (unsigned)__cvta_generic_to_shared(Ks);
    const uint32_t VsA = (unsigned)__cvta_generic_to_shared(Vs);

    int st = 0;
    for (int kt = 0; kt < 32; ++kt) {
        if (kt < 31) CP_WAIT1(); else CP_WAIT0();
        __syncthreads();
        if (kt < 30) {
            int st2 = st + 2; if (st2 >= 3) st2 -= 3;
            KV_LOAD(kt+2, st2); CP_COMMIT();
        }
        const uint32_t ksb = KsA + st*64*72*2;
        const uint32_t vsb = VsA + st*64*72*2;
        const int k0 = kt*64;

        // S = Q K^T : 32x64 in registers; each K fragment used by both row-halves
        float sc[2][8][4];
        #pragma unroll
        for (int r2 = 0; r2 < 2; ++r2)
            #pragma unroll
            for (int j = 0; j < 8; ++j) { sc[r2][j][0]=0.f; sc[r2][j][1]=0.f; sc[r2][j][2]=0.f; sc[r2][j][3]=0.f; }
        #pragma unroll
        for (int kk = 0; kk < 4; ++kk) {
            #pragma unroll
            for (int jj = 0; jj < 4; ++jj) {
                uint32_t kb[4];
                ldm_x4(kb, ksb + ((jj*16 + brow)*72 + kk*16 + bc8*8)*2);
                #pragma unroll
                for (int r2 = 0; r2 < 2; ++r2) {
                    mma16816(sc[r2][jj*2],   qa[kk][r2], kb[0], kb[1]);
                    mma16816(sc[r2][jj*2+1], qa[kk][r2], kb[2], kb[3]);
                }
            }
        }

        // exp2(S + bias) -> half2 P fragments
        uint32_t ph[2][8][2];
        #pragma unroll
        for (int r2 = 0; r2 < 2; ++r2)
            #pragma unroll
            for (int j = 0; j < 8; ++j) {
                float2 bv = *(const float2*)&bias[k0 + j*8 + t4*2];
                float p0 = exp2f(sc[r2][j][0] + bv.x);
                float p1 = exp2f(sc[r2][j][1] + bv.y);
                float p2 = exp2f(sc[r2][j][2] + bv.x);
                float p3 = exp2f(sc[r2][j][3] + bv.y);
                rsv[r2][0] += p0 + p1;
                rsv[r2][1] += p2 + p3;
                __half2 h0 = __floats2half2_rn(p0, p1);
                __half2 h1 = __floats2half2_rn(p2, p3);
                ph[r2][j][0] = *(uint32_t*)&h0;
                ph[r2][j][1] = *(uint32_t*)&h1;
            }

        // O += P V : each V fragment used by both row-halves
        #pragma unroll
        for (int kp = 0; kp < 4; ++kp) {
            #pragma unroll
            for (int jj = 0; jj < 4; ++jj) {
                uint32_t vb[4];
                ldm_x4_t(vb, vsb + ((kp*16 + arow)*72 + jj*16 + ac8*8)*2);
                #pragma unroll
                for (int r2 = 0; r2 < 2; ++r2) {
                    uint32_t pa[4] = { ph[r2][2*kp][0], ph[r2][2*kp][1], ph[r2][2*kp+1][0], ph[r2][2*kp+1][1] };
                    mma16816(oc[r2][jj*2],   pa, vb[0], vb[1]);
                    mma16816(oc[r2][jj*2+1], pa, vb[2], vb[3]);
                }
            }
        }
        if (++st == 3) st = 0;
    }

    // normalize and write ctx
    #pragma unroll
    for (int r2 = 0; r2 < 2; ++r2) {
        float rs0 = rsv[r2][0], rs1 = rsv[r2][1];
        rs0 += __shfl_xor_sync(0xffffffffu, rs0, 1);
        rs0 += __shfl_xor_sync(0xffffffffu, rs0, 2);
        rs1 += __shfl_xor_sync(0xffffffffu, rs1, 1);
        rs1 += __shfl_xor_sync(0xffffffffu, rs1, 2);
        float inv0 = 1.f / rs0;
        float inv1 = 1.f / rs1;
        __half* d0 = g_ctxh + ((size_t)(b*SS + q0 + w*32 + r2*16 + g    ))*DD + h*DHH;
        __half* d1 = g_ctxh + ((size_t)(b*SS + q0 + w*32 + r2*16 + g + 8))*DD + h*DHH;
        #pragma unroll
        for (int j = 0; j < 8; ++j) {
            __half2 u0 = __floats2half2_rn(oc[r2][j][0]*inv0, oc[r2][j][1]*inv0);
            __half2 u1 = __floats2half2_rn(oc[r2][j][2]*inv1, oc[r2][j][3]*inv1);
            *(__half2*)&d0[j*8 + t4*2] = u0;
            *(__half2*)&d1[j*8 + t4*2] = u1;
        }
    }
}

// ---------------- host launcher ----------------------------------------------
static void* symaddr(const void* sym) { void* p = 0; cudaGetSymbolAddress(&p, sym); return p; }

#define GEMM_SMEM 73728
#define ATTN_SMEM 81920

extern "C" void kernel_launch(void* const* d_in, const int* in_sizes, int n_in,
                              void* d_out, int out_size) {
    const float* x   = (const float*)d_in[0];
    const int*   mask= (const int*)  d_in[1];
    const float* Wq  = (const float*)d_in[2];
    const float* bq  = (const float*)d_in[3];
    const float* Wk  = (const float*)d_in[4];
    const float* bk  = (const float*)d_in[5];
    const float* Wv  = (const float*)d_in[6];
    const float* bv  = (const float*)d_in[7];
    const float* Wo  = (const float*)d_in[8];
    const float* bo  = (const float*)d_in[9];
    const float* Wm1 = (const float*)d_in[10];
    const float* bm1 = (const float*)d_in[11];
    const float* Wm2 = (const float*)d_in[12];
    float* out = (float*)d_out;

    __half* xh   = (__half*)symaddr(g_xh);
    __half* Wqh  = (__half*)symaddr(g_Wqh);
    __half* Wkh  = (__half*)symaddr(g_Wkh);
    __half* Wvh  = (__half*)symaddr(g_Wvh);
    __half* Woh  = (__half*)symaddr(g_Woh);
    __half* Wm1h = (__half*)symaddr(g_Wm1h);
    __half* ctxh = (__half*)symaddr(g_ctxh);

    cudaFuncSetAttribute(gemm_kernel, cudaFuncAttributeMaxDynamicSharedMemorySize, GEMM_SMEM);
    cudaFuncSetAttribute(attn_kernel, cudaFuncAttributeMaxDynamicSharedMemorySize, ATTN_SMEM);

    // 1. convert all fp32 inputs to fp16 in one launch
    f2h_all_kernel<<<(C5 + 255)/256, 256>>>(
        (const float4*)x, (const float4*)Wq, (const float4*)Wk,
        (const float4*)Wv, (const float4*)Wo, (const float4*)Wm1);

    // 2. merged QKV + mech-MLP GEMM (z=0..2: QKV; z=3: mech layer1+GELU+logits partials)
    gemm_kernel<<<dim3(MM/128, DD/128, 4), 256, GEMM_SMEM>>>(
        xh, Wqh, Wkh, Wvh, Wm1h, bq, bk, bv, bm1, Wm2, 0, 0);

    // 3. mech softmax (sums logits partials; bm2 cancels in softmax)
    mech_softmax_kernel<<<BB, 256>>>(out + (size_t)MM*DD);

    // 4. attention (4 warps x 32 q-rows, 128 threads)
    attn_kernel<<<dim3(SS/128, BB*HH), 128, ATTN_SMEM>>>(mask);

    // 5. output projection -> d_out
    gemm_kernel<<<dim3(MM/128, DD/128, 1), 256, GEMM_SMEM>>>(
        (const __half*)ctxh, Woh, Woh, Woh, Woh, bo, bo, bo, bo, Wm2, out, 1);
}

// round 15
// speedup vs baseline: 1.1178x; 1.0200x over previous
#include <cuda_runtime.h>
#include <cuda_fp16.h>
#include <mma.h>
#include <cstdint>

using namespace nvcuda;

// Problem constants
#define BB   2
#define SS   2048
#define DD   1024
#define HH   16
#define DHH  64
#define MM   (BB*SS)          // 4096
#define DHID 512              // mech hidden

#define LOG2E 1.44269504088896340736f

// ---------------- scratch (device globals; no allocation allowed) -------------
__device__ __half g_xh  [MM*DD];
__device__ __half g_Wqh [DD*DD];
__device__ __half g_Wkh [DD*DD];
__device__ __half g_Wvh [DD*DD];
__device__ __half g_Woh [DD*DD];
__device__ __half g_Wm1h[DHID*DD];
__device__ __half g_Qh  [MM*DD];   // [b*H+h][S][64]  (Q pre-scaled by log2e/8)
__device__ __half g_Kh  [MM*DD];
__device__ __half g_Vh  [MM*DD];
__device__ __half g_ctxh[MM*DD];   // [b][s][h*64+d]
__device__ float  g_part[4][MM];   // per-block logits partials (deterministic)
__device__ float  g_mech[MM];

// ---------------- cp.async helpers -------------------------------------------
__device__ __forceinline__ void cp16(void* s, const void* g) {
    asm volatile("cp.async.ca.shared.global [%0], [%1], 16;"
                 :: "r"((unsigned)__cvta_generic_to_shared(s)), "l"(g));
}
#define CP_COMMIT() asm volatile("cp.async.commit_group;")
#define CP_WAIT0()  asm volatile("cp.async.wait_group 0;")
#define CP_WAIT1()  asm volatile("cp.async.wait_group 1;")

// ---------------- mma.sync helpers --------------------------------------------
__device__ __forceinline__ void ldm_x4(uint32_t r[4], uint32_t addr) {
    asm volatile("ldmatrix.sync.aligned.m8n8.x4.shared.b16 {%0,%1,%2,%3}, [%4];"
                 : "=r"(r[0]), "=r"(r[1]), "=r"(r[2]), "=r"(r[3]) : "r"(addr));
}
__device__ __forceinline__ void ldm_x4_t(uint32_t r[4], uint32_t addr) {
    asm volatile("ldmatrix.sync.aligned.m8n8.x4.trans.shared.b16 {%0,%1,%2,%3}, [%4];"
                 : "=r"(r[0]), "=r"(r[1]), "=r"(r[2]), "=r"(r[3]) : "r"(addr));
}
__device__ __forceinline__ void mma16816(float c[4], const uint32_t a[4], uint32_t b0, uint32_t b1) {
    asm volatile("mma.sync.aligned.m16n8k16.row.col.f32.f16.f16.f32 "
                 "{%0,%1,%2,%3}, {%4,%5,%6,%7}, {%8,%9}, {%0,%1,%2,%3};"
                 : "+f"(c[0]), "+f"(c[1]), "+f"(c[2]), "+f"(c[3])
                 : "r"(a[0]), "r"(a[1]), "r"(a[2]), "r"(a[3]), "r"(b0), "r"(b1));
}

// ---------------- fp32 -> fp16 convert (single merged launch) ------------------
#define N4_X   (MM*DD/4)
#define N4_W   (DD*DD/4)
#define N4_WM1 (DHID*DD/4)
#define C0 N4_X
#define C1 (C0 + N4_W)
#define C2 (C1 + N4_W)
#define C3 (C2 + N4_W)
#define C4 (C3 + N4_W)
#define C5 (C4 + N4_WM1)
__global__ void f2h_all_kernel(
    const float4* __restrict__ x,  const float4* __restrict__ wq, const float4* __restrict__ wk,
    const float4* __restrict__ wv, const float4* __restrict__ wo, const float4* __restrict__ wm1)
{
    int i = blockIdx.x * blockDim.x + threadIdx.x;
    const float4* src; uint2* dst; int off;
    if      (i < C0) { src = x;   dst = (uint2*)g_xh;   off = i;      }
    else if (i < C1) { src = wq;  dst = (uint2*)g_Wqh;  off = i - C0; }
    else if (i < C2) { src = wk;  dst = (uint2*)g_Wkh;  off = i - C1; }
    else if (i < C3) { src = wv;  dst = (uint2*)g_Wvh;  off = i - C2; }
    else if (i < C4) { src = wo;  dst = (uint2*)g_Woh;  off = i - C3; }
    else if (i < C5) { src = wm1; dst = (uint2*)g_Wm1h; off = i - C4; }
    else return;
    float4 v = src[off];
    __half2 h0 = __floats2half2_rn(v.x, v.y);
    __half2 h1 = __floats2half2_rn(v.z, v.w);
    dst[off] = make_uint2(*(unsigned*)&h0, *(unsigned*)&h1);
}

// ---------------- 128x128-tile GEMM, 4 warps x (64m x 64n): C = A*W^T + b ------
// 128 threads; per warp per k-step: 8 fragment loads feed 16 wmma (4x/4x reuse).
// mode 0: merged launch, grid z=0..3:
//   z=0/1/2: QKV projections (half out, head-split; Q scaled by log2e/8)
//   z=3 (y<4 only): mech layer1 + GELU + dot(Wm2) -> g_part[y][m]  (fused logits)
// mode 1: fp32 out row-major (output projection; uses Wa/ba)
__global__ void __launch_bounds__(128) gemm_kernel(
    const __half* __restrict__ A,
    const __half* __restrict__ Wa, const __half* __restrict__ Wb,
    const __half* __restrict__ Wc, const __half* __restrict__ Wd,
    const float*  __restrict__ ba, const float*  __restrict__ bb,
    const float*  __restrict__ bc, const float*  __restrict__ bd,
    const float*  __restrict__ Wm2,
    float* __restrict__ outF, int mode)
{
    bool mech = false;
    if (mode == 0 && blockIdx.z == 3) {
        if (blockIdx.y >= DHID/128) return;    // mech N=512: only y<4
        mech = true;
    }

    extern __shared__ __align__(16) char dyn[];
    __half* As = (__half*)dyn;           // 2 * 128*72
    __half* Bs = As + 2*128*72;          // 2 * 128*72
    float*  Cs = (float*)dyn;            // epilogue reuse: 128*132 floats

    const __half* Wp = Wa;
    const float*  bp = ba;
    __half* dstH = 0;
    float scale = 1.f;
    if (mode == 0) {
        int z = blockIdx.z;
        if (mech) { Wp = Wd; bp = bd; }
        else {
            Wp   = (z==0) ? Wa : (z==1) ? Wb : Wc;
            bp   = (z==0) ? ba : (z==1) ? bb : bc;
            dstH = (z==0) ? g_Qh : (z==1) ? g_Kh : g_Vh;
            scale = (z==0) ? 0.125f * LOG2E : 1.f;
        }
    }

    const int m0 = blockIdx.x * 128;
    const int n0 = blockIdx.y * 128;
    const int tid = threadIdx.x;
    const int wid = tid >> 5;
    const int wr  = wid & 1;       // m: 2 x 64
    const int wc  = wid >> 1;      // n: 2 x 64

    wmma::fragment<wmma::accumulator,16,16,16,float> acc[4][4];
    #pragma unroll
    for (int i = 0; i < 4; ++i)
        #pragma unroll
        for (int j = 0; j < 4; ++j) wmma::fill_fragment(acc[i][j], 0.f);

    // stage loader: 2048 16B-chunks per stage / 128 threads = 16 per thread
    #define GEMM_LOAD(kt, st) do {                                                  \
        const int k0_ = (kt)*64;                                                    \
        __half* as_ = As + (st)*128*72;                                             \
        __half* bs_ = Bs + (st)*128*72;                                             \
        _Pragma("unroll")                                                           \
        for (int i_ = 0; i_ < 8; ++i_) {                                            \
            int idx_ = tid + i_*128;            /* 0..1023 */                       \
            int r_ = idx_ >> 3, c8_ = idx_ & 7;                                     \
            cp16(as_ + r_*72 + c8_*8, A  + (size_t)(m0+r_)*1024 + k0_ + c8_*8);     \
            cp16(bs_ + r_*72 + c8_*8, Wp + (size_t)(n0+r_)*1024 + k0_ + c8_*8);     \
        }                                                                           \
    } while(0)

    GEMM_LOAD(0, 0); CP_COMMIT();

    for (int kt = 0; kt < 16; ++kt) {
        CP_WAIT0();
        __syncthreads();
        if (kt < 15) { GEMM_LOAD(kt+1, (kt+1)&1); CP_COMMIT(); }
        const __half* as = As + (kt&1)*128*72;
        const __half* bs = Bs + (kt&1)*128*72;
        #pragma unroll
        for (int kk = 0; kk < 4; ++kk) {
            wmma::fragment<wmma::matrix_a,16,16,16,__half,wmma::row_major> af[4];
            #pragma unroll
            for (int fm = 0; fm < 4; ++fm)
                wmma::load_matrix_sync(af[fm], as + (wr*64 + fm*16)*72 + kk*16, 72);
            #pragma unroll
            for (int fn = 0; fn < 4; ++fn) {
                wmma::fragment<wmma::matrix_b,16,16,16,__half,wmma::col_major> bf;
                wmma::load_matrix_sync(bf, bs + (wc*64 + fn*16)*72 + kk*16, 72);
                #pragma unroll
                for (int fm = 0; fm < 4; ++fm)
                    wmma::mma_sync(acc[fm][fn], af[fm], bf, acc[fm][fn]);
            }
        }
    }
    __syncthreads();

    #pragma unroll
    for (int fm = 0; fm < 4; ++fm)
        #pragma unroll
        for (int fn = 0; fn < 4; ++fn)
            wmma::store_matrix_sync(Cs + (wr*64 + fm*16)*132 + wc*64 + fn*16, acc[fm][fn], 132, wmma::mem_row_major);
    __syncthreads();

    // epilogue: thread tid handles row tid, all 128 cols
    const int row = tid;
    const int m   = m0 + row;
    if (mode == 1) {
        float* dst = outF + (size_t)m*DD + n0;
        #pragma unroll
        for (int c = 0; c < 128; ++c)
            dst[c] = Cs[row*132 + c] + bp[n0 + c];
    } else if (!mech) {
        int b = m >> 11, s = m & 2047;
        #pragma unroll
        for (int hc = 0; hc < 2; ++hc) {
            int h = (n0 >> 6) + hc;
            __half* dst = dstH + (((size_t)(b*HH + h))*SS + s)*DHH;
            #pragma unroll
            for (int c0 = 0; c0 < 64; c0 += 8) {
                __half hv[8];
                #pragma unroll
                for (int e = 0; e < 8; ++e)
                    hv[e] = __float2half((Cs[row*132 + hc*64 + c0 + e] + bp[n0 + hc*64 + c0 + e]) * scale);
                *(uint4*)&dst[c0] = *(uint4*)hv;
            }
        }
    } else {
        // mech: GELU then full-row dot with Wm2; deterministic per-block partial
        float p = 0.f;
        #pragma unroll
        for (int c = 0; c < 128; ++c) {
            int n = n0 + c;
            float v = Cs[row*132 + c] + bp[n];
            float gl = 0.5f * v * (1.f + erff(v * 0.70710678118654752f));
            p += gl * Wm2[n];
        }
        g_part[blockIdx.y][m] = p;
    }
}

// ---------------- per-batch softmax over S=2048 (sums the 4 logits partials) ---
__global__ void mech_softmax_kernel(float* __restrict__ out_tail) {
    int b = blockIdx.x;
    int tid = threadIdx.x;           // 256
    __shared__ float red[256];
    __shared__ float lg[SS];
    for (int i = tid; i < SS; i += 256) {
        int m = b*SS + i;
        lg[i] = g_part[0][m] + g_part[1][m] + g_part[2][m] + g_part[3][m];
    }
    __syncthreads();
    float mx = -1e30f;
    for (int i = tid; i < SS; i += 256) mx = fmaxf(mx, lg[i]);
    red[tid] = mx; __syncthreads();
    for (int s = 128; s > 0; s >>= 1) { if (tid < s) red[tid] = fmaxf(red[tid], red[tid+s]); __syncthreads(); }
    mx = red[0]; __syncthreads();
    float sm = 0.f;
    for (int i = tid; i < SS; i += 256) sm += __expf(lg[i] - mx);
    red[tid] = sm; __syncthreads();
    for (int s = 128; s > 0; s >>= 1) { if (tid < s) red[tid] += red[tid+s]; __syncthreads(); }
    float inv = 1.f / red[0];
    for (int i = tid; i < SS; i += 256) {
        float v = __expf(lg[i] - mx) * inv;
        g_mech[b*SS + i] = v;
        out_tail[b*SS + i] = v;
    }
}

// ---------------- attention: 4 warps x 32 q-rows (K/V fragment reuse 2x) -------
// 128 queries/block, 128 threads, 64-key tiles, 3-stage cp.async KV ring.
// smem: Qs 128x72h | Ks 3x64x72h | Vs 3x64x72h | bias 2048f = 81920 B; 2 CTAs/SM.
__global__ void __launch_bounds__(128, 2) attn_kernel(const int* __restrict__ mask) {
    extern __shared__ __align__(16) char dyn[];
    __half* Qs  = (__half*)dyn;              // 128*72
    __half* Ks  = Qs + 128*72;               // 3*64*72
    __half* Vs  = Ks + 3*64*72;              // 3*64*72
    float*  bias= (float*)(Vs + 3*64*72);    // 2048

    const int q0  = blockIdx.x * 128;
    const int bh  = blockIdx.y;
    const int b   = bh >> 4;
    const int h   = bh & 15;
    const int tid = threadIdx.x;
    const int w   = tid >> 5;          // 0..3, owns rows [w*32, w*32+32)
    const int lane= tid & 31;
    const int g   = lane >> 2;
    const int t4  = lane & 3;

    const int arow = (lane & 7) | (((lane >> 3) & 1) << 3);
    const int ac8  = lane >> 4;
    const int brow = (lane & 7) | ((lane >> 4) << 3);
    const int bc8  = (lane >> 3) & 1;

    const __half* Qg = g_Qh + (size_t)bh * SS * DHH;
    const __half* Kg = g_Kh + (size_t)bh * SS * DHH;
    const __half* Vg = g_Vh + (size_t)bh * SS * DHH;

    #pragma unroll
    for (int i = 0; i < 8; ++i) {
        int idx = tid + i*128;
        int r = idx >> 3, c8 = idx & 7;
        *(uint4*)(Qs + r*72 + c8*8) = *(const uint4*)(Qg + (size_t)(q0+r)*DHH + c8*8);
    }
    for (int i = tid; i < SS; i += 128)
        bias[i] = mask[b*SS + i] ? (2.0f * LOG2E) * g_mech[b*SS + i] : -1e30f;

    #define KV_LOAD(kt, st) do {                                                  \
        const int k0_ = (kt)*64;                                                  \
        __half* ks_ = Ks + (st)*64*72;                                            \
        __half* vs_ = Vs + (st)*64*72;                                            \
        _Pragma("unroll")                                                         \
        for (int i_ = 0; i_ < 4; ++i_) {                                          \
            int idx_ = tid + i_*128;                                              \
            int r_ = idx_ >> 3, c8_ = idx_ & 7;                                   \
            cp16(ks_ + r_*72 + c8_*8, Kg + (size_t)(k0_+r_)*DHH + c8_*8);         \
            cp16(vs_ + r_*72 + c8_*8, Vg + (size_t)(k0_+r_)*DHH + c8_*8);         \
        }                                                                         \
    } while(0)

    KV_LOAD(0, 0); CP_COMMIT();
    KV_LOAD(1, 1); CP_COMMIT();
    __syncthreads();                 // Q + bias visible

    uint32_t qa[4][2][4];
    #pragma unroll
    for (int kk = 0; kk < 4; ++kk)
        #pragma unroll
        for (int r2 = 0; r2 < 2; ++r2) {
            uint32_t addr = (unsigned)__cvta_generic_to_shared(
                Qs + (w*32 + r2*16 + arow)*72 + kk*16 + ac8*8);
            ldm_x4(qa[kk][r2], addr);
        }

    float oc[2][8][4];
    #pragma unroll
    for (int r2 = 0; r2 < 2; ++r2)
        #pragma unroll
        for (int j = 0; j < 8; ++j) { oc[r2][j][0]=0.f; oc[r2][j][1]=0.f; oc[r2][j][2]=0.f; oc[r2][j][3]=0.f; }
    float rsv[2][2] = {{0.f,0.f},{0.f,0.f}};

    const uint32_t KsA = (unsigned)__cvta_generic_to_shared(Ks);
    const uint32_t VsA = (unsigned)__cvta_generic_to_shared(Vs);

    int st = 0;
    for (int kt = 0; kt < 32; ++kt) {
        if (kt < 31) CP_WAIT1(); else CP_WAIT0();
        __syncthreads();
        if (kt < 30) {
            int st2 = st + 2; if (st2 >= 3) st2 -= 3;
            KV_LOAD(kt+2, st2); CP_COMMIT();
        }
        const uint32_t ksb = KsA + st*64*72*2;
        const uint32_t vsb = VsA + st*64*72*2;
        const int k0 = kt*64;

        float sc[2][8][4];
        #pragma unroll
        for (int r2 = 0; r2 < 2; ++r2)
            #pragma unroll
            for (int j = 0; j < 8; ++j) { sc[r2][j][0]=0.f; sc[r2][j][1]=0.f; sc[r2][j][2]=0.f; sc[r2][j][3]=0.f; }
        #pragma unroll
        for (int kk = 0; kk < 4; ++kk) {
            #pragma unroll
            for (int jj = 0; jj < 4; ++jj) {
                uint32_t kb[4];
                ldm_x4(kb, ksb + ((jj*16 + brow)*72 + kk*16 + bc8*8)*2);
                #pragma unroll
                for (int r2 = 0; r2 < 2; ++r2) {
                    mma16816(sc[r2][jj*2],   qa[kk][r2], kb[0], kb[1]);
                    mma16816(sc[r2][jj*2+1], qa[kk][r2], kb[2], kb[3]);
                }
            }
        }

        uint32_t ph[2][8][2];
        #pragma unroll
        for (int r2 = 0; r2 < 2; ++r2)
            #pragma unroll
            for (int j = 0; j < 8; ++j) {
                float2 bv = *(const float2*)&bias[k0 + j*8 + t4*2];
                float p0 = exp2f(sc[r2][j][0] + bv.x);
                float p1 = exp2f(sc[r2][j][1] + bv.y);
                float p2 = exp2f(sc[r2][j][2] + bv.x);
                float p3 = exp2f(sc[r2][j][3] + bv.y);
                rsv[r2][0] += p0 + p1;
                rsv[r2][1] += p2 + p3;
                __half2 h0 = __floats2half2_rn(p0, p1);
                __half2 h1 = __floats2half2_rn(p2, p3);
                ph[r2][j][0] = *(uint32_t*)&h0;
                ph[r2][j][1] = *(uint32_t*)&h1;
            }

        #pragma unroll
        for (int kp = 0; kp < 4; ++kp) {
            #pragma unroll
            for (int jj = 0; jj < 4; ++jj) {
                uint32_t vb[4];
                ldm_x4_t(vb, vsb + ((kp*16 + arow)*72 + jj*16 + ac8*8)*2);
                #pragma unroll
                for (int r2 = 0; r2 < 2; ++r2) {
                    uint32_t pa[4] = { ph[r2][2*kp][0], ph[r2][2*kp][1], ph[r2][2*kp+1][0], ph[r2][2*kp+1][1] };
                    mma16816(oc[r2][jj*2],   pa, vb[0], vb[1]);
                    mma16816(oc[r2][jj*2+1], pa, vb[2], vb[3]);
                }
            }
        }
        if (++st == 3) st = 0;
    }

    #pragma unroll
    for (int r2 = 0; r2 < 2; ++r2) {
        float rs0 = rsv[r2][0], rs1 = rsv[r2][1];
        rs0 += __shfl_xor_sync(0xffffffffu, rs0, 1);
        rs0 += __shfl_xor_sync(0xffffffffu, rs0, 2);
        rs1 += __shfl_xor_sync(0xffffffffu, rs1, 1);
        rs1 += __shfl_xor_sync(0xffffffffu, rs1, 2);
        float inv0 = 1.f / rs0;
        float inv1 = 1.f / rs1;
        __half* d0 = g_ctxh + ((size_t)(b*SS + q0 + w*32 + r2*16 + g    ))*DD + h*DHH;
        __half* d1 = g_ctxh + ((size_t)(b*SS + q0 + w*32 + r2*16 + g + 8))*DD + h*DHH;
        #pragma unroll
        for (int j = 0; j < 8; ++j) {
            __half2 u0 = __floats2half2_rn(oc[r2][j][0]*inv0, oc[r2][j][1]*inv0);
            __half2 u1 = __floats2half2_rn(oc[r2][j][2]*inv1, oc[r2][j][3]*inv1);
            *(__half2*)&d0[j*8 + t4*2] = u0;
            *(__half2*)&d1[j*8 + t4*2] = u1;
        }
    }
}

// ---------------- host launcher ----------------------------------------------
static void* symaddr(const void* sym) { void* p = 0; cudaGetSymbolAddress(&p, sym); return p; }

#define GEMM_SMEM 73728
#define ATTN_SMEM 81920

extern "C" void kernel_launch(void* const* d_in, const int* in_sizes, int n_in,
                              void* d_out, int out_size) {
    const float* x   = (const float*)d_in[0];
    const int*   mask= (const int*)  d_in[1];
    const float* Wq  = (const float*)d_in[2];
    const float* bq  = (const float*)d_in[3];
    const float* Wk  = (const float*)d_in[4];
    const float* bk  = (const float*)d_in[5];
    const float* Wv  = (const float*)d_in[6];
    const float* bv  = (const float*)d_in[7];
    const float* Wo  = (const float*)d_in[8];
    const float* bo  = (const float*)d_in[9];
    const float* Wm1 = (const float*)d_in[10];
    const float* bm1 = (const float*)d_in[11];
    const float* Wm2 = (const float*)d_in[12];
    float* out = (float*)d_out;

    __half* xh   = (__half*)symaddr(g_xh);
    __half* Wqh  = (__half*)symaddr(g_Wqh);
    __half* Wkh  = (__half*)symaddr(g_Wkh);
    __half* Wvh  = (__half*)symaddr(g_Wvh);
    __half* Woh  = (__half*)symaddr(g_Woh);
    __half* Wm1h = (__half*)symaddr(g_Wm1h);
    __half* ctxh = (__half*)symaddr(g_ctxh);

    cudaFuncSetAttribute(gemm_kernel, cudaFuncAttributeMaxDynamicSharedMemorySize, GEMM_SMEM);
    cudaFuncSetAttribute(attn_kernel, cudaFuncAttributeMaxDynamicSharedMemorySize, ATTN_SMEM);

    // 1. convert all fp32 inputs to fp16 in one launch
    f2h_all_kernel<<<(C5 + 255)/256, 256>>>(
        (const float4*)x, (const float4*)Wq, (const float4*)Wk,
        (const float4*)Wv, (const float4*)Wo, (const float4*)Wm1);

    // 2. merged QKV + mech-MLP GEMM (z=0..2: QKV; z=3: mech layer1+GELU+logits partials)
    gemm_kernel<<<dim3(MM/128, DD/128, 4), 128, GEMM_SMEM>>>(
        xh, Wqh, Wkh, Wvh, Wm1h, bq, bk, bv, bm1, Wm2, 0, 0);

    // 3. mech softmax (sums logits partials; bm2 cancels in softmax)
    mech_softmax_kernel<<<BB, 256>>>(out + (size_t)MM*DD);

    // 4. attention (4 warps x 32 q-rows, 128 threads)
    attn_kernel<<<dim3(SS/128, BB*HH), 128, ATTN_SMEM>>>(mask);

    // 5. output projection -> d_out
    gemm_kernel<<<dim3(MM/128, DD/128, 1), 128, GEMM_SMEM>>>(
        (const __half*)ctxh, Woh, Woh, Woh, Woh, bo, bo, bo, bo, Wm2, out, 1);
}